// round 9
// baseline (speedup 1.0000x reference)
#include <cuda_runtime.h>

#define HH 96
#define WW 128
#define CC 21
#define NPIX (HH*WW)   // 12288
#define NITER 5

// ---------------- scratch ----------------
__device__ float g_kt[48];       // truncated profile: exp(-(j-24)^2/18), 0 beyond r=16
__device__ float g_rSx[WW];      // exact full-kernel normalizers
__device__ float g_rSy[HH];
__device__ float g_A[CC*CC];     // compat @ (Ws + Wb)
__device__ float g_ut[CC*NPIX];  // unaries transposed  [c][x*96+y]
__device__ float g_r [CC*NPIX];  // r = A @ softmax(q)  [c][x*96+y]
__device__ float g_t1[CC*NPIX];  // after y-blur        [c][y*128+x]
__device__ float g_q [CC*NPIX];  // q = u - blur(r)*nrm [c][x*96+y]

// ======== init: tables + (softmax(u), ut, r=A@p), warp-autonomous ========
// grid 392 x 128: blocks 0..383 pixel work (32 px each); 384..391 tables.
__global__ void init_kernel(const float* __restrict__ un,
                            const float* __restrict__ Ws,
                            const float* __restrict__ Wb,
                            const float* __restrict__ Cm) {
    const float inv18 = 1.0f / 18.0f;
    if (blockIdx.x >= 384) {
        int idx = (blockIdx.x - 384) * 128 + threadIdx.x;
        int total = 48 + WW + HH + CC*CC;           // 713
        if (idx < total) {
            int i = idx;
            if (i < 48) {
                float d = fabsf((float)(i - 24));
                g_kt[i] = (d <= 16.0f) ? expf(-d * d * inv18) : 0.0f;
            } else if (i < 48 + WW) {
                int x = i - 48;
                float s = 0.0f;
                for (int xp = 0; xp < WW; xp++) {
                    float d = (float)(x - xp); s += expf(-d * d * inv18);
                }
                g_rSx[x] = 1.0f / s;
            } else if (i < 48 + WW + HH) {
                int y = i - (48 + WW);
                float s = 0.0f;
                for (int yp = 0; yp < HH; yp++) {
                    float d = (float)(y - yp); s += expf(-d * d * inv18);
                }
                g_rSy[y] = 1.0f / s;
            } else {
                int a = i - (48 + WW + HH);
                int rr = a / CC, cc = a % CC;
                float s = 0.0f;
                for (int k = 0; k < CC; k++)
                    s += Cm[rr*CC + k] * (Ws[k*CC + cc] + Wb[k*CC + cc]);
                g_A[a] = s;
            }
        }
        return;
    }
    __shared__ float sA[CC*CC];
    __shared__ float sp[32*21];     // [px-in-block][c], stride 21 (odd -> conflict-free)
    int t = threadIdx.x;
    for (int a = t; a < CC*CC; a += 128) {          // local A (g_A not ready yet)
        int rr = a / CC, cc = a % CC;
        float s = 0.0f;
        for (int k = 0; k < CC; k++)
            s += Cm[rr*CC + k] * (Ws[k*CC + cc] + Wb[k*CC + cc]);
        sA[a] = s;
    }
    __syncthreads();                                // only block barrier

    int lane = t & 31, w = t >> 5;
    int pxw = lane >> 2, sub = lane & 3;            // 8 px/warp, 4 subs/px
    int px  = w * 8 + pxw;                          // 0..31
    int m   = blockIdx.x * 32 + px;                 // m = x*96 + y
    int y = m % HH, x = m / HH;
    const float* ub = un + (y * WW + x) * CC;       // NHWC pixel (one-time scatter)
    int nc    = (sub == 3) ? 6 : 5;
    int cbase = sub * 5;

    float v[6]; float mx = -1e30f;
    #pragma unroll
    for (int k = 0; k < 6; k++)
        if (k < nc) {
            v[k] = ub[cbase + k]; mx = fmaxf(mx, v[k]);
            g_ut[(cbase + k)*NPIX + m] = v[k];
        }
    mx = fmaxf(mx, __shfl_xor_sync(0xffffffffu, mx, 1));
    mx = fmaxf(mx, __shfl_xor_sync(0xffffffffu, mx, 2));
    float sum = 0.0f;
    #pragma unroll
    for (int k = 0; k < 6; k++)
        if (k < nc) { v[k] = __expf(v[k] - mx); sum += v[k]; }
    sum += __shfl_xor_sync(0xffffffffu, sum, 1);
    sum += __shfl_xor_sync(0xffffffffu, sum, 2);
    float rinv = 1.0f / sum;
    #pragma unroll
    for (int k = 0; k < 6; k++)
        if (k < nc) sp[px*21 + cbase + k] = v[k] * rinv;
    __syncwarp();                                   // warp-local only

    float acc[6] = {0.f,0.f,0.f,0.f,0.f,0.f};
    #pragma unroll
    for (int cp = 0; cp < CC; cp++) {
        float pv = sp[px*21 + cp];
        #pragma unroll
        for (int k = 0; k < 6; k++) acc[k] += sA[(cbase + k)*CC + cp] * pv;
    }
    #pragma unroll
    for (int k = 0; k < 6; k++)
        if (k < nc) g_r[(cbase + k)*NPIX + m] = acc[k];
}

// ======== y-blur (radius 16): t1[c][y][x] = sum_yp r[c][x][yp]*k(|yp-y|) ========
__global__ void blury_kernel() {
    __shared__ float skt[64];
    __shared__ float sp[16 * 129];                  // [col][yp+16], zero-padded
    int tid = threadIdx.x;
    int c  = blockIdx.y;
    int x0 = blockIdx.x * 16;
    if (tid < 64) skt[tid] = (tid < 48) ? g_kt[tid] : 0.0f;
    #pragma unroll
    for (int i = tid; i < 512; i += 256) {          // zero pads [0,16) & [112,128)
        int col = i >> 5, off = i & 31;
        sp[col*129 + (off < 16 ? off : off + 96)] = 0.0f;
    }
    const float* pc = g_r + c*NPIX + x0*96;
    #pragma unroll
    for (int i = tid; i < 16 * 24; i += 256) {
        int col = i / 24, j = i % 24;
        float4 v = *(const float4*)(pc + col*96 + j*4);
        float* d = &sp[col*129 + 16 + j*4];
        d[0] = v.x; d[1] = v.y; d[2] = v.z; d[3] = v.w;
    }
    __syncthreads();

    int lx = tid & 15, ty = tid >> 4;
    int y0 = ty * 6;
    const float* spv = &sp[lx * 129];
    float acc[6] = {0.f,0.f,0.f,0.f,0.f,0.f};
    float w[6];
    #pragma unroll
    for (int k = 0; k < 6; k++) w[k] = skt[8 - k];
    #pragma unroll
    for (int j = 8; j < 46; j++) {                  // 38 taps
        float v = spv[y0 + j - 8];
        #pragma unroll
        for (int k = 0; k < 6; k++) acc[k] += v * w[k];
        #pragma unroll
        for (int k = 5; k > 0; k--) w[k] = w[k-1];
        w[0] = skt[j + 1];
    }
    float* tb = g_t1 + c*NPIX + y0*128 + x0 + lx;
    #pragma unroll
    for (int k = 0; k < 6; k++) tb[k * 128] = acc[k];
}

// ======== x-blur (radius 16) + norm + update; last iter emits NHWC out ========
__global__ void blurx_kernel(float* __restrict__ out, int last) {
    __shared__ float skt[64];
    __shared__ float st[16 * 161];                  // [row][xp+16], zero-padded
    __shared__ float ss[128 * 17];                  // staged transpose [x][row]
    int tid = threadIdx.x;
    int c   = blockIdx.y;
    int y0b = blockIdx.x * 16;
    if (tid < 64) skt[tid] = (tid < 48) ? g_kt[tid] : 0.0f;
    #pragma unroll
    for (int i = tid; i < 512; i += 256) {          // zero pads [0,16) & [144,160)
        int r = i >> 5, off = i & 31;
        st[r*161 + (off < 16 ? off : off + 128)] = 0.0f;
    }
    const float* tc = g_t1 + c*NPIX + y0b*128;
    #pragma unroll
    for (int i = tid; i < 16 * 32; i += 256) {
        int r = i >> 5, j = i & 31;
        float4 v = *(const float4*)(tc + r*128 + j*4);
        float* d = &st[r*161 + 16 + j*4];
        d[0] = v.x; d[1] = v.y; d[2] = v.z; d[3] = v.w;
    }
    __syncthreads();

    int xt = tid & 15, r = tid >> 4;
    int x0 = xt * 8;
    const float* stv = &st[r * 161];
    float acc[8] = {0.f,0.f,0.f,0.f,0.f,0.f,0.f,0.f};
    float w[8];
    #pragma unroll
    for (int k = 0; k < 8; k++) w[k] = skt[8 - k];
    #pragma unroll
    for (int j = 8; j < 48; j++) {                  // 40 taps
        float v = stv[x0 + j - 8];
        #pragma unroll
        for (int k = 0; k < 8; k++) acc[k] += v * w[k];
        #pragma unroll
        for (int k = 7; k > 0; k--) w[k] = w[k-1];
        w[0] = skt[j + 1];
    }

    float rn_y = g_rSy[y0b + r];
    #pragma unroll
    for (int k = 0; k < 8; k++)
        ss[(x0 + k) * 17 + r] = acc[k] * g_rSx[x0 + k] * rn_y;
    __syncthreads();

    if (last) {
        const float* utb = g_ut + c*NPIX + y0b;
        for (int i = tid; i < 2048; i += 256) {
            int x = i >> 4, yy = i & 15;
            float u = utb[x*96 + yy];
            out[(x*HH + y0b + yy)*CC + c] = u - ss[x*17 + yy];
        }
    } else {
        const float* utb = g_ut + c*NPIX + y0b;
        float*       qb  = g_q  + c*NPIX + y0b;
        #pragma unroll
        for (int i = tid; i < 512; i += 256) {
            int x = i >> 2, qq = i & 3;
            const float* p4 = &ss[x * 17 + qq * 4];
            float4 u4 = *(const float4*)(utb + x*96 + qq*4);
            float4 v = make_float4(u4.x - p4[0], u4.y - p4[1],
                                   u4.z - p4[2], u4.w - p4[3]);
            *(float4*)(qb + x*96 + qq*4) = v;
        }
    }
}

// ======== pix: p = softmax(q); r = A @ p — warp-autonomous ========
// grid 384, block 128: warp = 8 px x 4 subs (lane = px*4+sub).
// One __syncthreads (sA load); everything else warp-local shfl/syncwarp.
__global__ void pix_kernel() {
    __shared__ float sA[CC*CC];
    __shared__ float sp[32*21];
    int t = threadIdx.x;
    for (int a = t; a < CC*CC; a += 128) sA[a] = g_A[a];
    __syncthreads();

    int lane = t & 31, w = t >> 5;
    int pxw = lane >> 2, sub = lane & 3;
    int px  = w * 8 + pxw;
    int m   = blockIdx.x * 32 + px;
    int nc    = (sub == 3) ? 6 : 5;
    int cbase = sub * 5;

    float v[6]; float mx = -1e30f;
    #pragma unroll
    for (int k = 0; k < 6; k++)
        if (k < nc) { v[k] = g_q[(cbase + k)*NPIX + m]; mx = fmaxf(mx, v[k]); }
    mx = fmaxf(mx, __shfl_xor_sync(0xffffffffu, mx, 1));
    mx = fmaxf(mx, __shfl_xor_sync(0xffffffffu, mx, 2));
    float sum = 0.0f;
    #pragma unroll
    for (int k = 0; k < 6; k++)
        if (k < nc) { v[k] = __expf(v[k] - mx); sum += v[k]; }
    sum += __shfl_xor_sync(0xffffffffu, sum, 1);
    sum += __shfl_xor_sync(0xffffffffu, sum, 2);
    float rinv = 1.0f / sum;
    #pragma unroll
    for (int k = 0; k < 6; k++)
        if (k < nc) sp[px*21 + cbase + k] = v[k] * rinv;
    __syncwarp();

    float acc[6] = {0.f,0.f,0.f,0.f,0.f,0.f};
    #pragma unroll
    for (int cp = 0; cp < CC; cp++) {
        float pv = sp[px*21 + cp];                  // 8 distinct banks + broadcast
        #pragma unroll
        for (int k = 0; k < 6; k++) acc[k] += sA[(cbase + k)*CC + cp] * pv;
    }
    #pragma unroll
    for (int k = 0; k < 6; k++)
        if (k < nc) g_r[(cbase + k)*NPIX + m] = acc[k];
}

extern "C" void kernel_launch(void* const* d_in, const int* in_sizes, int n_in,
                              void* d_out, int out_size) {
    const float* un = (const float*)d_in[0];
    // d_in[1] = rgb: provably unused (bilateral term replaced by spatial in source)
    const float* Ws = (const float*)d_in[2];
    const float* Wb = (const float*)d_in[3];
    const float* Cm = (const float*)d_in[4];
    float* out = (float*)d_out;

    init_kernel<<<392, 128>>>(un, Ws, Wb, Cm);
    for (int it = 0; it < NITER; it++) {
        blury_kernel<<<dim3(8, 21), 256>>>();
        blurx_kernel<<<dim3(6, 21), 256>>>(out, (it == NITER - 1) ? 1 : 0);
        if (it < NITER - 1) pix_kernel<<<384, 128>>>();
    }
}

// round 10
// speedup vs baseline: 1.0415x; 1.0415x over previous
#include <cuda_runtime.h>

#define HH 96
#define WW 128
#define CC 21
#define NPIX (HH*WW)   // 12288
#define NITER 5

// ---------------- scratch ----------------
__device__ __align__(16) float g_kt[48];       // truncated profile, 0 beyond r=16
__device__ __align__(16) float g_rSx[WW];      // exact full-kernel normalizers
__device__ __align__(16) float g_rSy[HH];
__device__ __align__(16) float g_A[CC*CC];     // compat @ (Ws + Wb)
__device__ __align__(16) float g_ut2[CC*NPIX]; // unaries transposed [c][y*128+x]
__device__ __align__(16) float g_r [CC*NPIX];  // r = A @ softmax(q) [c][y*128+x]
__device__ __align__(16) float g_t1[CC*NPIX];  // after y-blur       [c][y*128+x]

// ======== init: tables + (softmax(u), ut2, r=A@p) ========
// grid 392 x 128: blocks 0..383 pixel work (32 px, x-fastest n); 384..391 tables.
__global__ void init_kernel(const float* __restrict__ un,
                            const float* __restrict__ Ws,
                            const float* __restrict__ Wb,
                            const float* __restrict__ Cm) {
    const float inv18 = 1.0f / 18.0f;
    if (blockIdx.x >= 384) {
        int idx = (blockIdx.x - 384) * 128 + threadIdx.x;
        int total = 48 + WW + HH + CC*CC;           // 713
        if (idx < total) {
            int i = idx;
            if (i < 48) {
                float d = fabsf((float)(i - 24));
                g_kt[i] = (d <= 16.0f) ? expf(-d * d * inv18) : 0.0f;
            } else if (i < 48 + WW) {
                int x = i - 48;
                float s = 0.0f;
                for (int xp = 0; xp < WW; xp++) {
                    float d = (float)(x - xp); s += expf(-d * d * inv18);
                }
                g_rSx[x] = 1.0f / s;
            } else if (i < 48 + WW + HH) {
                int y = i - (48 + WW);
                float s = 0.0f;
                for (int yp = 0; yp < HH; yp++) {
                    float d = (float)(y - yp); s += expf(-d * d * inv18);
                }
                g_rSy[y] = 1.0f / s;
            } else {
                int a = i - (48 + WW + HH);
                int rr = a / CC, cc = a % CC;
                float s = 0.0f;
                for (int k = 0; k < CC; k++)
                    s += Cm[rr*CC + k] * (Ws[k*CC + cc] + Wb[k*CC + cc]);
                g_A[a] = s;
            }
        }
        return;
    }
    __shared__ float sA[CC*CC];
    __shared__ float sp[32*21];
    int t = threadIdx.x;
    for (int a = t; a < CC*CC; a += 128) {          // local A (g_A not ready yet)
        int rr = a / CC, cc = a % CC;
        float s = 0.0f;
        for (int k = 0; k < CC; k++)
            s += Cm[rr*CC + k] * (Ws[k*CC + cc] + Wb[k*CC + cc]);
        sA[a] = s;
    }
    __syncthreads();

    int lane = t & 31, w = t >> 5;
    int pxw = lane >> 2, sub = lane & 3;            // 8 px/warp, 4 subs/px
    int px  = w * 8 + pxw;
    int n   = blockIdx.x * 32 + px;                 // n = y*128 + x (x-fastest)
    const float* ub = un + n * CC;                  // NHWC: contiguous per pixel
    int nc    = (sub == 3) ? 6 : 5;
    int cbase = sub * 5;

    float v[6]; float mx = -1e30f;
    #pragma unroll
    for (int k = 0; k < 6; k++)
        if (k < nc) {
            v[k] = ub[cbase + k]; mx = fmaxf(mx, v[k]);
            g_ut2[(cbase + k)*NPIX + n] = v[k];
        }
    mx = fmaxf(mx, __shfl_xor_sync(0xffffffffu, mx, 1));
    mx = fmaxf(mx, __shfl_xor_sync(0xffffffffu, mx, 2));
    float sum = 0.0f;
    #pragma unroll
    for (int k = 0; k < 6; k++)
        if (k < nc) { v[k] = __expf(v[k] - mx); sum += v[k]; }
    sum += __shfl_xor_sync(0xffffffffu, sum, 1);
    sum += __shfl_xor_sync(0xffffffffu, sum, 2);
    float rinv = 1.0f / sum;
    #pragma unroll
    for (int k = 0; k < 6; k++)
        if (k < nc) sp[px*21 + cbase + k] = v[k] * rinv;
    __syncwarp();

    float acc[6] = {0.f,0.f,0.f,0.f,0.f,0.f};
    #pragma unroll
    for (int cp = 0; cp < CC; cp++) {
        float pv = sp[px*21 + cp];
        #pragma unroll
        for (int k = 0; k < 6; k++) acc[k] += sA[(cbase + k)*CC + cp] * pv;
    }
    #pragma unroll
    for (int k = 0; k < 6; k++)
        if (k < nc) g_r[(cbase + k)*NPIX + n] = acc[k];
}

// ======== y-blur (radius 16): t1[c][y][x] = sum_yp r[c][yp][x]*k(|yp-y|) ========
// grid (8,21), block 256 = 16 x-cols x 16 thread-rows; thread computes 6 y outputs.
__global__ void blury_kernel() {
    __shared__ float skt[64];
    __shared__ float sp[16 * 129];                  // [xi][yp+16], zero-padded
    int tid = threadIdx.x;
    int c  = blockIdx.y;
    int x0 = blockIdx.x * 16;
    if (tid < 64) skt[tid] = (tid < 48) ? g_kt[tid] : 0.0f;
    #pragma unroll
    for (int i = tid; i < 512; i += 256) {          // zero pads [0,16) & [112,128)
        int col = i >> 5, off = i & 31;
        sp[col*129 + (off < 16 ? off : off + 96)] = 0.0f;
    }
    const float* pc = g_r + c*NPIX + x0;            // x-fastest source
    #pragma unroll
    for (int i = tid; i < 1536; i += 256) {         // 96 y-rows x 16 x (64B segs)
        int yy = i >> 4, xi = i & 15;
        sp[xi*129 + 16 + yy] = pc[yy*128 + xi];
    }
    __syncthreads();

    int lx = tid & 15, ty = tid >> 4;
    int y0 = ty * 6;
    const float* spv = &sp[lx * 129];
    float acc[6] = {0.f,0.f,0.f,0.f,0.f,0.f};
    float w[6];
    #pragma unroll
    for (int k = 0; k < 6; k++) w[k] = skt[8 - k];
    #pragma unroll
    for (int j = 8; j < 46; j++) {                  // 38 taps
        float v = spv[y0 + j - 8 + 16 - 16];        // sp offset folded below
        v = spv[y0 + j + 8 - 16];                   // = sp[lx][16 + (y0+j-8) - 16]
        #pragma unroll
        for (int k = 0; k < 6; k++) acc[k] += v * w[k];
        #pragma unroll
        for (int k = 5; k > 0; k--) w[k] = w[k-1];
        w[0] = skt[j + 1];
    }
    float* tb = g_t1 + c*NPIX + y0*128 + x0 + lx;
    #pragma unroll
    for (int k = 0; k < 6; k++) tb[k * 128] = acc[k];
}

// ======== fused x-blur + update + softmax + A-matvec (or emit) ========
// grid 96 (one y-row each), block 256. smem ~26KB.
__global__ void blurxpix_kernel(float* __restrict__ out, int last) {
    __shared__ float skt[64];
    __shared__ float sA[CC*CC];
    __shared__ float st[CC * 161];                  // [c][xp+16], zero-padded
    __shared__ float sq[128 * CC];                  // q then p, [x][c]
    int tid = threadIdx.x;
    int y = blockIdx.x;
    if (tid < 64) skt[tid] = (tid < 48) ? g_kt[tid] : 0.0f;
    for (int a = tid; a < CC*CC; a += 256) sA[a] = g_A[a];
    for (int i = tid; i < CC*32; i += 256) {        // zero pads [0,16) & [144,160)
        int cc = i >> 5, o = i & 31;
        st[cc*161 + (o < 16 ? o : o + 128)] = 0.0f;
    }
    for (int i = tid; i < CC*32; i += 256) {        // t1 row y, all classes (float4)
        int cc = i >> 5, j = i & 31;
        float4 v = *(const float4*)(g_t1 + cc*NPIX + y*128 + j*4);
        float* d = &st[cc*161 + 16 + j*4];
        d[0] = v.x; d[1] = v.y; d[2] = v.z; d[3] = v.w;
    }
    __syncthreads();

    float rn_y = g_rSy[y];
    // blur: 336 (c, x-tile) tasks, 8 outputs each, sliding weight window
    for (int tile = tid; tile < CC*16; tile += 256) {
        int cc = tile >> 4, xt = tile & 15;
        int x0 = xt * 8;
        const float* stv = &st[cc * 161];
        float acc[8] = {0.f,0.f,0.f,0.f,0.f,0.f,0.f,0.f};
        float w[8];
        #pragma unroll
        for (int k = 0; k < 8; k++) w[k] = skt[8 - k];
        #pragma unroll
        for (int j = 8; j < 48; j++) {              // 40 taps
            float v = stv[x0 + j - 8];
            #pragma unroll
            for (int k = 0; k < 8; k++) acc[k] += v * w[k];
            #pragma unroll
            for (int k = 7; k > 0; k--) w[k] = w[k-1];
            w[0] = skt[j + 1];
        }
        const float* ub = g_ut2 + cc*NPIX + y*128 + x0;
        #pragma unroll
        for (int k = 0; k < 8; k++)
            sq[(x0 + k)*CC + cc] = ub[k] - acc[k] * g_rSx[x0 + k] * rn_y;
    }
    __syncthreads();

    // pixel part: 2 lanes per pixel (lane pair via shfl xor 1)
    int px = tid >> 1, sub = tid & 1;               // px = x
    int nc    = sub ? 10 : 11;
    int cbase = sub ? 11 : 0;
    float* qrow = &sq[px * CC];

    if (last) {                                     // emit out[(x*96+y)*21+c]
        float* ob = out + (px*HH + y)*CC + cbase;
        #pragma unroll
        for (int k = 0; k < 11; k++)
            if (k < nc) ob[k] = qrow[cbase + k];
        return;
    }

    float v[11]; float mx = -1e30f;
    #pragma unroll
    for (int k = 0; k < 11; k++)
        if (k < nc) { v[k] = qrow[cbase + k]; mx = fmaxf(mx, v[k]); }
    mx = fmaxf(mx, __shfl_xor_sync(0xffffffffu, mx, 1));
    float sum = 0.0f;
    #pragma unroll
    for (int k = 0; k < 11; k++)
        if (k < nc) { v[k] = __expf(v[k] - mx); sum += v[k]; }
    sum += __shfl_xor_sync(0xffffffffu, sum, 1);
    float rinv = 1.0f / sum;
    #pragma unroll
    for (int k = 0; k < 11; k++)
        if (k < nc) qrow[cbase + k] = v[k] * rinv;  // overwrite q with p
    __syncwarp();                                   // both subs of px in same warp

    float acc[11];
    #pragma unroll
    for (int k = 0; k < 11; k++) acc[k] = 0.0f;
    #pragma unroll
    for (int cp = 0; cp < CC; cp++) {
        float pv = qrow[cp];
        #pragma unroll
        for (int k = 0; k < 11; k++)
            if (k < nc) acc[k] += sA[(cbase + k)*CC + cp] * pv;
    }
    #pragma unroll
    for (int k = 0; k < 11; k++)
        if (k < nc) g_r[(cbase + k)*NPIX + y*128 + px] = acc[k];
}

extern "C" void kernel_launch(void* const* d_in, const int* in_sizes, int n_in,
                              void* d_out, int out_size) {
    const float* un = (const float*)d_in[0];
    // d_in[1] = rgb: provably unused (bilateral term replaced by spatial in source)
    const float* Ws = (const float*)d_in[2];
    const float* Wb = (const float*)d_in[3];
    const float* Cm = (const float*)d_in[4];
    float* out = (float*)d_out;

    init_kernel<<<392, 128>>>(un, Ws, Wb, Cm);
    for (int it = 0; it < NITER; it++) {
        blury_kernel<<<dim3(8, 21), 256>>>();
        blurxpix_kernel<<<96, 256>>>(out, (it == NITER - 1) ? 1 : 0);
    }
}